// round 11
// baseline (speedup 1.0000x reference)
#include <cuda_runtime.h>
#include <cuda_bf16.h>
#include <cstdint>

#define N_NODES 100000
#define D_DIM   128
#define O_DIM   128
#define R_REL   4
#define E_EDGES 400000

// Per-relation scratch: y_r = x @ W_r, r = 0..3. 4 * 51.2 MB = 204.8 MB.
// Static __device__ scratch (no allocations allowed in kernel_launch).
__device__ float g_y4[R_REL * N_NODES * O_DIM];

// ---------------------------------------------------------------------------
// zero out (harness poisons d_out with 0xAA). N*O/4 = 3.2M float4 = 12500*256.
// ---------------------------------------------------------------------------
__global__ void zero_kernel(float4* __restrict__ out) {
    int i = blockIdx.x * 256 + threadIdx.x;
    out[i] = make_float4(0.f, 0.f, 0.f, 0.f);
}

// ---------------------------------------------------------------------------
// GEMM (all relations in one launch): y4[r][n][o] = sum_d x[n][d] * W[r][d][o]
// blockIdx.y = relation, blockIdx.x = 128-row tile. 256 threads, 8x8 micro-
// tile, K = 128 single pass. Inner product uses packed fma.rn.f32x2 (FFMA2):
// accumulators paired along columns, b-pairs free via LDS.128 register-pair
// aliasing, a splat per row. Numerics identical to scalar fp32 FFMA.
// ---------------------------------------------------------------------------
__global__ void __launch_bounds__(256) gemm_kernel(const float* __restrict__ x,
                                                   const float* __restrict__ Wall,
                                                   float* __restrict__ y4) {
    extern __shared__ float smem[];
    float* Ast = smem;               // [k][row]  128*128 (x tile, transposed)
    float* Bs  = smem + 128 * 128;   // [k][col]  128*128 (W tile)

    const int tid  = threadIdx.x;
    const int row0 = blockIdx.x * 128;
    const float* W = Wall + blockIdx.y * (D_DIM * O_DIM);
    float*       y = y4   + blockIdx.y * (N_NODES * O_DIM);

    // Load W tile: 4096 float4, 16 per thread, fully coalesced.
#pragma unroll
    for (int i = 0; i < 16; ++i) {
        int idx4 = tid + i * 256;             // 0..4095
        *(float4*)&Bs[idx4 * 4] = *(const float4*)&W[idx4 * 4];
    }

    // Load x tile transposed into Ast[k][row].
    // Lanes take consecutive rows at the same k4 -> STS conflict-free.
#pragma unroll
    for (int i = 0; i < 16; ++i) {
        int idx  = tid + i * 256;             // 0..4095
        int row  = idx & 127;
        int k4   = idx >> 7;                  // 0..31
        int grow = row0 + row;
        float4 v = make_float4(0.f, 0.f, 0.f, 0.f);
        if (grow < N_NODES) v = *(const float4*)&x[grow * 128 + k4 * 4];
        Ast[(4 * k4 + 0) * 128 + row] = v.x;
        Ast[(4 * k4 + 1) * 128 + row] = v.y;
        Ast[(4 * k4 + 2) * 128 + row] = v.z;
        Ast[(4 * k4 + 3) * 128 + row] = v.w;
    }
    __syncthreads();

    const int tx = (tid & 15) * 8;   // col offset within tile
    const int ty = (tid >> 4) * 8;   // row offset within tile

    // acc[i][j2] = packed pair {acc_f32[i][2*j2], acc_f32[i][2*j2+1]}
    unsigned long long acc[8][4];
#pragma unroll
    for (int i = 0; i < 8; ++i)
#pragma unroll
        for (int j = 0; j < 4; ++j) acc[i][j] = 0ull;

#pragma unroll 4
    for (int k = 0; k < 128; ++k) {
        float4 a0 = *(float4*)&Ast[k * 128 + ty];
        float4 a1 = *(float4*)&Ast[k * 128 + ty + 4];
        // b pairs: 16B LDS lands in aligned register pairs -> free f32x2 packs
        ulonglong2 bb0 = *(ulonglong2*)&Bs[k * 128 + tx];
        ulonglong2 bb1 = *(ulonglong2*)&Bs[k * 128 + tx + 4];
        unsigned long long b2[4] = {bb0.x, bb0.y, bb1.x, bb1.y};

        float a[8] = {a0.x, a0.y, a0.z, a0.w, a1.x, a1.y, a1.z, a1.w};
#pragma unroll
        for (int i = 0; i < 8; ++i) {
            unsigned long long a2;
            uint32_t ar = __float_as_uint(a[i]);
            asm("mov.b64 %0, {%1, %1};" : "=l"(a2) : "r"(ar));
#pragma unroll
            for (int j = 0; j < 4; ++j) {
                asm("fma.rn.f32x2 %0, %1, %2, %0;"
                    : "+l"(acc[i][j]) : "l"(a2), "l"(b2[j]));
            }
        }
    }

#pragma unroll
    for (int i = 0; i < 8; ++i) {
        int grow = row0 + ty + i;
        if (grow < N_NODES) {
            uint32_t lo[4], hi[4];
#pragma unroll
            for (int j = 0; j < 4; ++j)
                asm("mov.b64 {%0, %1}, %2;"
                    : "=r"(lo[j]), "=r"(hi[j]) : "l"(acc[i][j]));
            float4 v0 = make_float4(__uint_as_float(lo[0]), __uint_as_float(hi[0]),
                                    __uint_as_float(lo[1]), __uint_as_float(hi[1]));
            float4 v1 = make_float4(__uint_as_float(lo[2]), __uint_as_float(hi[2]),
                                    __uint_as_float(lo[3]), __uint_as_float(hi[3]));
            *(float4*)&y[grow * 128 + tx]     = v0;
            *(float4*)&y[grow * 128 + tx + 4] = v1;
        }
    }
}

// ---------------------------------------------------------------------------
// Scatter (all relations, one launch): for flat edge e (arrays are [R,E]
// contiguous): out[row_e][:] += val_e * y4[e/E][col_e][:]
// One warp per edge: lane covers 4 consecutive floats (512B coalesced read).
// y4 reads use .cs (streaming / evict-first) so the 205MB read stream does
// not evict the 51MB atomic destination from L2; one red.global.add.v4.f32
// per lane does the accumulation.
// ---------------------------------------------------------------------------
__global__ void __launch_bounds__(256) scatter_kernel(const int* __restrict__ erow,
                                                      const int* __restrict__ ecol,
                                                      const float* __restrict__ eval,
                                                      const float* __restrict__ y4,
                                                      float* __restrict__ out) {
    const int lane = threadIdx.x & 31;
    const int warp = threadIdx.x >> 5;
    const int e    = blockIdx.x * 8 + warp;      // 0 .. R*E-1 (exact grid)

    const int   rel = e / E_EDGES;               // const-div -> mul/shift
    const int   r   = erow[e];
    const int   c   = ecol[e];
    const float v   = eval[e];

    const float4* yrow = (const float4*)(y4 + (size_t)rel * (N_NODES * O_DIM)
                                            + (size_t)c * 128);
    float4 yv = __ldcs(yrow + lane);             // streaming load, evict-first
    float* op = &out[r * 128 + lane * 4];
    asm volatile("red.global.add.v4.f32 [%0], {%1, %2, %3, %4};"
                 :: "l"(op), "f"(v * yv.x), "f"(v * yv.y),
                    "f"(v * yv.z), "f"(v * yv.w)
                 : "memory");
}

// ---------------------------------------------------------------------------
extern "C" void kernel_launch(void* const* d_in, const int* in_sizes, int n_in,
                              void* d_out, int out_size) {
    const float* x    = (const float*)d_in[0];
    const int*   erow = (const int*)d_in[1];
    const int*   ecol = (const int*)d_in[2];
    const float* eval = (const float*)d_in[3];
    const float* W    = (const float*)d_in[4];
    float*       out  = (float*)d_out;

    cudaFuncSetAttribute(gemm_kernel,
                         cudaFuncAttributeMaxDynamicSharedMemorySize, 131072);

    // zero the output (poisoned to 0xAA by the harness); 12500*256 float4 exact
    zero_kernel<<<12500, 256>>>((float4*)out);

    float* yptr = nullptr;
    cudaGetSymbolAddress((void**)&yptr, g_y4);

    // all 4 relations in one GEMM launch (one wave tail instead of four)
    dim3 ggrid((N_NODES + 127) / 128, R_REL);
    gemm_kernel<<<ggrid, 256, 131072>>>(x, W, yptr);

    // all 1.6M edges in one scatter launch; R*E/8 = 200000 blocks exact
    scatter_kernel<<<(R_REL * E_EDGES) / 8, 256>>>(erow, ecol, eval, yptr, out);
}

// round 16
// speedup vs baseline: 1.0189x; 1.0189x over previous
#include <cuda_runtime.h>
#include <cuda_bf16.h>
#include <cstdint>

#define N_NODES 100000
#define D_DIM   128
#define O_DIM   128
#define R_REL   4
#define E_EDGES 400000

// Per-relation scratch: y_r = x @ W_r, r = 0..3. 4 * 51.2 MB = 204.8 MB.
// Static __device__ scratch (no allocations allowed in kernel_launch).
__device__ float g_y4[R_REL * N_NODES * O_DIM];

// ---------------------------------------------------------------------------
// GEMM (all relations in one launch): y4[r][n][o] = sum_d x[n][d] * W[r][d][o]
// blockIdx.y = relation, blockIdx.x = 128-row tile. 256 threads, 8x8 micro-
// tile, K = 128 single pass. Inner product uses packed fma.rn.f32x2 (FFMA2):
// accumulators paired along columns, b-pairs free via LDS.128 register-pair
// aliasing, a splat per row. Numerics identical to scalar fp32 FFMA.
// ---------------------------------------------------------------------------
__global__ void __launch_bounds__(256) gemm_kernel(const float* __restrict__ x,
                                                   const float* __restrict__ Wall,
                                                   float* __restrict__ y4) {
    extern __shared__ float smem[];
    float* Ast = smem;               // [k][row]  128*128 (x tile, transposed)
    float* Bs  = smem + 128 * 128;   // [k][col]  128*128 (W tile)

    const int tid  = threadIdx.x;
    const int row0 = blockIdx.x * 128;
    const float* W = Wall + blockIdx.y * (D_DIM * O_DIM);
    float*       y = y4   + blockIdx.y * (N_NODES * O_DIM);

    // Load W tile: 4096 float4, 16 per thread, fully coalesced.
#pragma unroll
    for (int i = 0; i < 16; ++i) {
        int idx4 = tid + i * 256;             // 0..4095
        *(float4*)&Bs[idx4 * 4] = *(const float4*)&W[idx4 * 4];
    }

    // Load x tile transposed into Ast[k][row].
    // Lanes take consecutive rows at the same k4 -> STS conflict-free.
#pragma unroll
    for (int i = 0; i < 16; ++i) {
        int idx  = tid + i * 256;             // 0..4095
        int row  = idx & 127;
        int k4   = idx >> 7;                  // 0..31
        int grow = row0 + row;
        float4 v = make_float4(0.f, 0.f, 0.f, 0.f);
        if (grow < N_NODES) v = *(const float4*)&x[grow * 128 + k4 * 4];
        Ast[(4 * k4 + 0) * 128 + row] = v.x;
        Ast[(4 * k4 + 1) * 128 + row] = v.y;
        Ast[(4 * k4 + 2) * 128 + row] = v.z;
        Ast[(4 * k4 + 3) * 128 + row] = v.w;
    }
    __syncthreads();

    const int tx = (tid & 15) * 8;   // col offset within tile
    const int ty = (tid >> 4) * 8;   // row offset within tile

    // acc[i][j2] = packed pair {acc_f32[i][2*j2], acc_f32[i][2*j2+1]}
    unsigned long long acc[8][4];
#pragma unroll
    for (int i = 0; i < 8; ++i)
#pragma unroll
        for (int j = 0; j < 4; ++j) acc[i][j] = 0ull;

#pragma unroll 4
    for (int k = 0; k < 128; ++k) {
        float4 a0 = *(float4*)&Ast[k * 128 + ty];
        float4 a1 = *(float4*)&Ast[k * 128 + ty + 4];
        // b pairs: 16B LDS lands in aligned register pairs -> free f32x2 packs
        ulonglong2 bb0 = *(ulonglong2*)&Bs[k * 128 + tx];
        ulonglong2 bb1 = *(ulonglong2*)&Bs[k * 128 + tx + 4];
        unsigned long long b2[4] = {bb0.x, bb0.y, bb1.x, bb1.y};

        float a[8] = {a0.x, a0.y, a0.z, a0.w, a1.x, a1.y, a1.z, a1.w};
#pragma unroll
        for (int i = 0; i < 8; ++i) {
            unsigned long long a2;
            uint32_t ar = __float_as_uint(a[i]);
            asm("mov.b64 %0, {%1, %1};" : "=l"(a2) : "r"(ar));
#pragma unroll
            for (int j = 0; j < 4; ++j) {
                asm("fma.rn.f32x2 %0, %1, %2, %0;"
                    : "+l"(acc[i][j]) : "l"(a2), "l"(b2[j]));
            }
        }
    }

#pragma unroll
    for (int i = 0; i < 8; ++i) {
        int grow = row0 + ty + i;
        if (grow < N_NODES) {
            uint32_t lo[4], hi[4];
#pragma unroll
            for (int j = 0; j < 4; ++j)
                asm("mov.b64 {%0, %1}, %2;"
                    : "=r"(lo[j]), "=r"(hi[j]) : "l"(acc[i][j]));
            float4 v0 = make_float4(__uint_as_float(lo[0]), __uint_as_float(hi[0]),
                                    __uint_as_float(lo[1]), __uint_as_float(hi[1]));
            float4 v1 = make_float4(__uint_as_float(lo[2]), __uint_as_float(hi[2]),
                                    __uint_as_float(lo[3]), __uint_as_float(hi[3]));
            *(float4*)&y[grow * 128 + tx]     = v0;
            *(float4*)&y[grow * 128 + tx + 4] = v1;
        }
    }
}

// ---------------------------------------------------------------------------
// Scatter (ONE relation per launch): out[row_e][:] += val_e * y[col_e][:]
// Working set per launch: y slice (51.2 MB) + out (51.2 MB) = 102.4 MB,
// co-resident in 126 MB L2 -> RMWs stay L2-local instead of DRAM round-trips.
// One warp per edge: lane covers 4 consecutive floats (512B coalesced read,
// default caching so repeated rows hit L2); one red.global.add.v4.f32/lane.
// ---------------------------------------------------------------------------
__global__ void __launch_bounds__(256) scatter_kernel(const int* __restrict__ erow,
                                                      const int* __restrict__ ecol,
                                                      const float* __restrict__ eval,
                                                      const float* __restrict__ y,
                                                      float* __restrict__ out) {
    const int lane = threadIdx.x & 31;
    const int warp = threadIdx.x >> 5;
    const int e    = blockIdx.x * 8 + warp;      // 0 .. E-1 (exact grid)

    const int   r = erow[e];
    const int   c = ecol[e];
    const float v = eval[e];

    const float4* yrow = (const float4*)(y + (size_t)c * 128);
    float4 yv = __ldg(yrow + lane);              // cached: y slice is L2-resident
    float* op = &out[r * 128 + lane * 4];
    asm volatile("red.global.add.v4.f32 [%0], {%1, %2, %3, %4};"
                 :: "l"(op), "f"(v * yv.x), "f"(v * yv.y),
                    "f"(v * yv.z), "f"(v * yv.w)
                 : "memory");
}

// ---------------------------------------------------------------------------
extern "C" void kernel_launch(void* const* d_in, const int* in_sizes, int n_in,
                              void* d_out, int out_size) {
    const float* x    = (const float*)d_in[0];
    const int*   erow = (const int*)d_in[1];
    const int*   ecol = (const int*)d_in[2];
    const float* eval = (const float*)d_in[3];
    const float* W    = (const float*)d_in[4];
    float*       out  = (float*)d_out;

    cudaFuncSetAttribute(gemm_kernel,
                         cudaFuncAttributeMaxDynamicSharedMemorySize, 131072);

    // zero the output (poisoned to 0xAA by the harness)
    cudaMemsetAsync(out, 0, (size_t)N_NODES * O_DIM * sizeof(float));

    float* yptr = nullptr;
    cudaGetSymbolAddress((void**)&yptr, g_y4);

    // all 4 relations in one GEMM launch (one wave tail instead of four)
    dim3 ggrid((N_NODES + 127) / 128, R_REL);
    gemm_kernel<<<ggrid, 256, 131072>>>(x, W, yptr);

    // relation-chunked scatter: y slice + out co-resident in L2.
    // E/8 = 50000 blocks exact per relation.
    for (int r = 0; r < R_REL; ++r) {
        scatter_kernel<<<E_EDGES / 8, 256>>>(
            erow + r * E_EDGES, ecol + r * E_EDGES, eval + r * E_EDGES,
            yptr + (size_t)r * N_NODES * O_DIM, out);
    }
}